// round 15
// baseline (speedup 1.0000x reference)
#include <cuda_runtime.h>
#include <cuda_fp16.h>

// SIREN fused inference, GB300 sm_103a — R15.
// R14 (771us): tensor 65%, 2 CTAs/SM — both CTAs often in epilogue at once.
// R15: 64-thread CTAs (2 warps, 32-pt tile), launch_bounds(64,4) -> 4
// independent phase-staggered CTAs/SM (same 8 warps, same per-warp work).
// More streams -> tensor-pipe gaps from one CTA's sine/split epilogue are
// filled by another's MMA bursts. Cost: 2x weight cp traffic (L2-hot, cheap).

#define THREADS 64
#define PTS     32
#define HID     128
#define NPTS    32768
#define BATCH   32
#define PARAMS_PER 50307
#define OMEGA0  30.0f

// pre-split fp16 weights, ldmatrix-block layout:
// per mat(96): 4 chunks(k32) x [hi 8KB | lo 8KB]; block addr (halves):
// kc*8192 + sel*4096 + ((ks*16+nt)*2+kb)*64 + r*8 + (k&7)
__device__ __half g_Wh[96 * 32768];

__constant__ int c_woff[3] = {384, 16896, 33408};

__device__ __forceinline__ unsigned smem_u32(const void* p) {
    return (unsigned)__cvta_generic_to_shared(p);
}
__device__ __forceinline__ void cp16(unsigned dst, const void* src) {
    asm volatile("cp.async.cg.shared.global [%0], [%1], 16;" :: "r"(dst), "l"(src));
}
__device__ __forceinline__ void cp_commit() { asm volatile("cp.async.commit_group;"); }
__device__ __forceinline__ void cp_wait0()  { asm volatile("cp.async.wait_group 0;"); }

__device__ __forceinline__ void ldsm2(unsigned& r0, unsigned& r1, unsigned addr) {
    asm volatile("ldmatrix.sync.aligned.m8n8.x2.shared.b16 {%0,%1}, [%2];"
                 : "=r"(r0), "=r"(r1) : "r"(addr));
}
__device__ __forceinline__ void mma16816(float* c, const unsigned* a,
                                         unsigned b0, unsigned b1) {
    asm volatile("mma.sync.aligned.m16n8k16.row.col.f32.f16.f16.f32 "
                 "{%0,%1,%2,%3}, {%4,%5,%6,%7}, {%8,%9}, {%0,%1,%2,%3};"
                 : "+f"(c[0]), "+f"(c[1]), "+f"(c[2]), "+f"(c[3])
                 : "r"(a[0]), "r"(a[1]), "r"(a[2]), "r"(a[3]), "r"(b0), "r"(b1));
}

// sine -> split fp16 hi/lo, packed as half2 (first arg in low half)
__device__ __forceinline__ void sin_split2(float z0, float z1,
                                           unsigned& hi, unsigned& lo) {
    float s0 = __sinf(OMEGA0 * z0), s1 = __sinf(OMEGA0 * z1);
    __half h0 = __float2half_rn(s0), h1 = __float2half_rn(s1);
    __half2 hp = __halves2half2(h0, h1);
    __half2 lp = __floats2half2_rn(s0 - __half2float(h0), s1 - __half2float(h1));
    hi = *(unsigned*)&hp;
    lo = *(unsigned*)&lp;
}

// ---------------- pre-pass: split W into fp16 hi/lo ldmatrix blocks --------
__global__ __launch_bounds__(256)
void wprep_kernel(const float* __restrict__ in0, const float* __restrict__ in1)
{
    const int t = threadIdx.x;
    const int in0_is_x = __syncthreads_or(fabsf(in0[t]) > 0.3f);
    const float* params = in0_is_x ? in1 : in0;

    const int mat = blockIdx.x;              // 0..95
    const int b = mat / 3, L = mat - 3 * b;
    const float* W = params + (size_t)b * PARAMS_PER + c_woff[L];  // [c][k]
    __half* dst = g_Wh + (size_t)mat * 32768;

    for (int i = 0; i < 64; i++) {
        int idx = t + 256 * i;               // c*128 + k
        int c = idx >> 7, k = idx & 127;
        float w = W[idx];
        __half h = __float2half_rn(w);
        __half l = __float2half_rn(w - __half2float(h));
        int kc = k >> 5, ks = (k >> 4) & 1, kb = (k >> 3) & 1;
        int nt = c >> 3, r = c & 7;
        int off = kc * 8192 + ((ks * 16 + nt) * 2 + kb) * 64 + r * 8 + (k & 7);
        dst[off]        = h;      // sel 0 (hi)
        dst[off + 4096] = l;      // sel 1 (lo)
    }
}

// ---------------- main fused tensor kernel ----------------
__global__ __launch_bounds__(THREADS, 4)
void siren_mma_kernel(const float* __restrict__ in0,
                      const float* __restrict__ in1,
                      float* __restrict__ out)
{
    __shared__ __align__(1024) __half WB[2][8192];   // 2 x 16KB chunk buffers
    __shared__ float SC[1184];                        // W1,b1,b2,b3,b4,W5,b5

    const int tid  = threadIdx.x;
    const int wid  = tid >> 5;    // 0..1
    const int lane = tid & 31;
    const int g    = lane >> 2;   // point row within warp tile
    const int t    = lane & 3;

    const int in0_is_x = __syncthreads_or(fabsf(in0[tid]) > 0.3f);
    const float* x      = in0_is_x ? in0 : in1;
    const float* params = in0_is_x ? in1 : in0;

    const int b   = blockIdx.y;
    const int pt0 = blockIdx.x * PTS;
    const float* p = params + (size_t)b * PARAMS_PER;
    const unsigned wbS = smem_u32(WB);

    // kick chunk 0 (layer 0) immediately: 16KB = 1024 float4, 16/thread
    {
        const float4* src = (const float4*)(g_Wh + (size_t)(b * 3) * 32768);
        #pragma unroll
        for (int it = 0; it < 16; it++)
            cp16(wbS + (tid + THREADS * it) * 16, src + tid + THREADS * it);
        cp_commit();
    }

    // stage scalars: [0:256) W1, [256:384) b1, [384:512) b2, [512:640) b3,
    // [640:768) b4, [768:1152) W5, [1152:1155) b5
    for (int i = tid; i < 1155; i += THREADS) {
        int gidx;
        if      (i < 384)  gidx = i;
        else if (i < 512)  gidx = 16768 + (i - 384);
        else if (i < 640)  gidx = 33280 + (i - 512);
        else if (i < 768)  gidx = 49792 + (i - 640);
        else if (i < 1152) gidx = 49920 + (i - 768);
        else               gidx = 50304 + (i - 1152);
        SC[i] = p[gidx];
    }
    __syncthreads();

    // ---- layer 1: build A fragments (hi/lo fp16) directly in registers ----
    unsigned ah[8][4], al[8][4];
    {
        const int m0 = pt0 + wid * 16 + g;
        float2 x0 = ((const float2*)x)[(size_t)b * NPTS + m0];
        float2 x1 = ((const float2*)x)[(size_t)b * NPTS + m0 + 8];
        #pragma unroll
        for (int kt = 0; kt < 8; kt++) {
            const int c0 = kt * 16 + 2 * t;
            const int c2 = c0 + 8;
            float za0 = fmaf(SC[2*c0],   x0.x, fmaf(SC[2*c0+1],   x0.y, SC[256+c0]));
            float za1 = fmaf(SC[2*c0+2], x0.x, fmaf(SC[2*c0+3],   x0.y, SC[256+c0+1]));
            float zb0 = fmaf(SC[2*c0],   x1.x, fmaf(SC[2*c0+1],   x1.y, SC[256+c0]));
            float zb1 = fmaf(SC[2*c0+2], x1.x, fmaf(SC[2*c0+3],   x1.y, SC[256+c0+1]));
            float zc0 = fmaf(SC[2*c2],   x0.x, fmaf(SC[2*c2+1],   x0.y, SC[256+c2]));
            float zc1 = fmaf(SC[2*c2+2], x0.x, fmaf(SC[2*c2+3],   x0.y, SC[256+c2+1]));
            float zd0 = fmaf(SC[2*c2],   x1.x, fmaf(SC[2*c2+1],   x1.y, SC[256+c2]));
            float zd1 = fmaf(SC[2*c2+2], x1.x, fmaf(SC[2*c2+3],   x1.y, SC[256+c2+1]));
            sin_split2(za0, za1, ah[kt][0], al[kt][0]);
            sin_split2(zb0, zb1, ah[kt][1], al[kt][1]);
            sin_split2(zc0, zc1, ah[kt][2], al[kt][2]);
            sin_split2(zd0, zd1, ah[kt][3], al[kt][3]);
        }
    }

    const unsigned lpart = (unsigned)((lane & 15) << 4);

    for (int L = 0; L < 3; L++) {
        // accumulators init = bias
        float acc[16][4];
        #pragma unroll
        for (int nt = 0; nt < 16; nt++) {
            float b0 = SC[384 + L * 128 + nt * 8 + 2 * t];
            float b1 = SC[384 + L * 128 + nt * 8 + 2 * t + 1];
            acc[nt][0] = b0; acc[nt][1] = b1; acc[nt][2] = b0; acc[nt][3] = b1;
        }

        #pragma unroll
        for (int kc = 0; kc < 4; kc++) {
            const int q = L * 4 + kc;
            cp_wait0();
            __syncthreads();
            if (q < 11) {   // issue next chunk into the other buffer
                const int qn = q + 1;
                const float4* src = (const float4*)(g_Wh
                    + (size_t)(b * 3 + (qn >> 2)) * 32768 + (size_t)(qn & 3) * 8192);
                unsigned dst = wbS + ((unsigned)(qn & 1) << 14);
                #pragma unroll
                for (int it = 0; it < 16; it++)
                    cp16(dst + (tid + THREADS * it) * 16, src + tid + THREADS * it);
                cp_commit();
            }

            const unsigned base = wbS + ((unsigned)(q & 1) << 14) + lpart;
            #pragma unroll
            for (int ks = 0; ks < 2; ks++) {
                const int kst = kc * 2 + ks;
                #pragma unroll
                for (int nt = 0; nt < 16; nt++) {
                    unsigned off = base + (unsigned)((ks * 16 + nt) * 256);
                    unsigned bh0, bh1, bl0, bl1;
                    ldsm2(bh0, bh1, off);
                    ldsm2(bl0, bl1, off + 8192);
                    mma16816(acc[nt], ah[kst], bh0, bh1);   // ah*wh
                    mma16816(acc[nt], al[kst], bh0, bh1);   // al*wh
                    mma16816(acc[nt], ah[kst], bl0, bl1);   // ah*wl
                }
            }
        }

        if (L < 2) {
            // epilogue: sine + split; C frags become next layer's A frags
            #pragma unroll
            for (int kt = 0; kt < 8; kt++) {
                sin_split2(acc[2*kt][0],   acc[2*kt][1],   ah[kt][0], al[kt][0]);
                sin_split2(acc[2*kt][2],   acc[2*kt][3],   ah[kt][1], al[kt][1]);
                sin_split2(acc[2*kt+1][0], acc[2*kt+1][1], ah[kt][2], al[kt][2]);
                sin_split2(acc[2*kt+1][2], acc[2*kt+1][3], ah[kt][3], al[kt][3]);
            }
        } else {
            // final: sine(layer4) fused with layer5 (128->3) via quad shuffles
            float p00 = 0.f, p01 = 0.f, p02 = 0.f;   // point row g
            float p10 = 0.f, p11 = 0.f, p12 = 0.f;   // point row g+8
            #pragma unroll
            for (int nt = 0; nt < 16; nt++) {
                const int c0 = nt * 8 + 2 * t;
                const int c1 = c0 + 1;
                float s0 = __sinf(OMEGA0 * acc[nt][0]);
                float s1 = __sinf(OMEGA0 * acc[nt][1]);
                float s2 = __sinf(OMEGA0 * acc[nt][2]);
                float s3 = __sinf(OMEGA0 * acc[nt][3]);
                p00 = fmaf(SC[768 + c0],       s0, fmaf(SC[768 + c1],       s1, p00));
                p01 = fmaf(SC[768 + 128 + c0], s0, fmaf(SC[768 + 128 + c1], s1, p01));
                p02 = fmaf(SC[768 + 256 + c0], s0, fmaf(SC[768 + 256 + c1], s1, p02));
                p10 = fmaf(SC[768 + c0],       s2, fmaf(SC[768 + c1],       s3, p10));
                p11 = fmaf(SC[768 + 128 + c0], s2, fmaf(SC[768 + 128 + c1], s3, p11));
                p12 = fmaf(SC[768 + 256 + c0], s2, fmaf(SC[768 + 256 + c1], s3, p12));
            }
            #pragma unroll
            for (int d = 1; d <= 2; d <<= 1) {
                p00 += __shfl_xor_sync(0xFFFFFFFF, p00, d);
                p01 += __shfl_xor_sync(0xFFFFFFFF, p01, d);
                p02 += __shfl_xor_sync(0xFFFFFFFF, p02, d);
                p10 += __shfl_xor_sync(0xFFFFFFFF, p10, d);
                p11 += __shfl_xor_sync(0xFFFFFFFF, p11, d);
                p12 += __shfl_xor_sync(0xFFFFFFFF, p12, d);
            }
            if (t == 0) {
                const int m0 = pt0 + wid * 16 + g;
                size_t o0 = ((size_t)b * NPTS + m0) * 3;
                size_t o1 = ((size_t)b * NPTS + m0 + 8) * 3;
                out[o0]     = p00 + SC[1152];
                out[o0 + 1] = p01 + SC[1153];
                out[o0 + 2] = p02 + SC[1154];
                out[o1]     = p10 + SC[1152];
                out[o1 + 1] = p11 + SC[1153];
                out[o1 + 2] = p12 + SC[1154];
            }
        }
    }
}

extern "C" void kernel_launch(void* const* d_in, const int* in_sizes, int n_in,
                              void* d_out, int out_size)
{
    const float* in0 = (const float*)d_in[0];
    const float* in1 = (const float*)d_in[1];
    float* out = (float*)d_out;   // [32, 32768, 3]

    wprep_kernel<<<BATCH * 3, 256>>>(in0, in1);

    dim3 grid(NPTS / PTS, BATCH);   // (1024, 32)
    siren_mma_kernel<<<grid, THREADS>>>(in0, in1, out);
}